// round 1
// baseline (speedup 1.0000x reference)
#include <cuda_runtime.h>

// ReprojectionLayer: project 40^3 grid thru 12 cameras, distort, clip,
// trilinear-upsample coords to 80^3, gather 23 joint heatmaps, mean over cams.

#define NC 12
#define NJ 23
#define HS 130
#define HS2 (HS*HS)       // 16900
#define G  80
#define G2 40
#define G3 (G*G*G)        // 512000

// Block tile of the 80^3 output
#define TI 8
#define TJ 8
#define TK 16
// Source (40^3) patch needed: T/2 + 2 per axis
#define SI 6
#define SJ 6
#define SK 10
#define NSRC (SI*SJ*SK)   // 360
#define NTHREADS 512      // each thread handles 2 voxels of the 8x8x16 tile

__global__ __launch_bounds__(NTHREADS)
void reproj_kernel(const float* __restrict__ heat,    // (C,J,HS,HS)
                   const float* __restrict__ center,  // (3)
                   const float* __restrict__ cHM,     // (C,2)
                   const float* __restrict__ Pm,      // (C,4,3)
                   const float* __restrict__ Km,      // (C,3,3)
                   const float* __restrict__ Dm,      // (C,1,5)
                   float* __restrict__ out)           // (J,G,G,G)
{
    __shared__ float sv1[NC][NSRC];
    __shared__ float sv2[NC][NSRC];

    const int tid = threadIdx.x;
    const int bI = blockIdx.z * TI;
    const int bJ = blockIdx.y * TJ;
    const int bK = blockIdx.x * TK;
    const int si0 = bI/2 - 1;   // raw source base (may be -1)
    const int sj0 = bJ/2 - 1;
    const int sk0 = bK/2 - 1;

    const float c0 = center[0], c1 = center[1], c2 = center[2];

    // ---- Phase 1: project the 40^3 source patch for all cameras into smem ----
    for (int t = tid; t < NC*NSRC; t += NTHREADS) {
        int c   = t / NSRC;
        int r   = t - c*NSRC;
        int i   = r / (SJ*SK);
        int rem = r - i*(SJ*SK);
        int jj  = rem / SK;
        int kk  = rem - jj*SK;
        int gi = min(max(si0 + i,  0), G2-1);
        int gj = min(max(sj0 + jj, 0), G2-1);
        int gk = min(max(sk0 + kk, 0), G2-1);
        float X = (float)(gi - 20) * 4.0f + c0;
        float Y = (float)(gj - 20) * 4.0f + c1;
        float Z = (float)(gk - 20) * 4.0f + c2;
        const float* P = Pm + c*12;
        float p0 = X*P[0] + Y*P[3] + Z*P[6] + P[9];
        float p1 = X*P[1] + Y*P[4] + Z*P[7] + P[10];
        float p2 = X*P[2] + Y*P[5] + Z*P[8] + P[11];
        const float* Kc = Km + c*9;
        float fx = Kc[0], fy = Kc[4], cx = Kc[6], cy = Kc[7];
        float k1 = Dm[c*5+0], k2 = Dm[c*5+1];
        float v1 = p0/p2 - cx;
        float v2 = p1/p2 - cy;
        float ra = v1/fx, rb = v2/fy;
        float r2 = ra*ra + rb*rb;
        float dist = 1.0f + (k1 + k2*r2)*r2;
        v1 = v1*dist + cx;
        v2 = v2*dist + cy;
        float chx = cHM[c*2+0], chy = cHM[c*2+1];
        v1 = fminf(fmaxf(v1, chx - 129.0f), chx + 128.0f) - chx + 129.0f;
        v2 = fminf(fmaxf(v2, chy - 129.0f), chy + 128.0f) - chy + 129.0f;
        sv1[c][r] = v1;
        sv2[c][r] = v2;
    }
    __syncthreads();

    // ---- Phase 2: 2 output voxels per thread ----
    #pragma unroll 1
    for (int s = 0; s < 2; s++) {
        int lv = tid + s*NTHREADS;
        int li = lv >> 7;          // / (TJ*TK)
        int lj = (lv >> 4) & 7;
        int lk = lv & 15;
        int I  = bI + li;
        int Jo = bJ + lj;
        int K  = bK + lk;

        // per-axis interp index + weight (matches align_corners=False upsample2x)
        int i0g, i1g, j0g, j1g, k0g, k1g;
        float wi, wj, wk;
        if (I == 0)        { i0g = 0;      i1g = 1;      wi = 0.f; }
        else if (I == G-1) { i0g = G2-1;   i1g = G2-1;   wi = 0.f; }
        else               { i0g = (I-1)>>1; i1g = i0g+1; wi = (I&1) ? 0.25f : 0.75f; }
        if (Jo == 0)        { j0g = 0;      j1g = 1;      wj = 0.f; }
        else if (Jo == G-1) { j0g = G2-1;   j1g = G2-1;   wj = 0.f; }
        else                { j0g = (Jo-1)>>1; j1g = j0g+1; wj = (Jo&1) ? 0.25f : 0.75f; }
        if (K == 0)        { k0g = 0;      k1g = 1;      wk = 0.f; }
        else if (K == G-1) { k0g = G2-1;   k1g = G2-1;   wk = 0.f; }
        else               { k0g = (K-1)>>1; k1g = k0g+1; wk = (K&1) ? 0.25f : 0.75f; }

        const int a0 = (i0g - si0)*(SJ*SK);
        const int a1 = (i1g - si0)*(SJ*SK);
        const int b0 = (j0g - sj0)*SK;
        const int b1 = (j1g - sj0)*SK;
        const int d0 = k0g - sk0;
        const int d1 = k1g - sk0;
        const float omwi = 1.0f - wi, omwj = 1.0f - wj, omwk = 1.0f - wk;

        int off[NC];
        #pragma unroll
        for (int c = 0; c < NC; c++) {
            const float* s1 = sv1[c];
            float t000 = s1[a0+b0+d0], t100 = s1[a1+b0+d0];
            float t010 = s1[a0+b1+d0], t110 = s1[a1+b1+d0];
            float t001 = s1[a0+b0+d1], t101 = s1[a1+b0+d1];
            float t011 = s1[a0+b1+d1], t111 = s1[a1+b1+d1];
            float u00 = t000*omwi + t100*wi;
            float u10 = t010*omwi + t110*wi;
            float u01 = t001*omwi + t101*wi;
            float u11 = t011*omwi + t111*wi;
            float w0  = u00*omwj + u10*wj;
            float w1  = u01*omwj + u11*wj;
            float V1  = w0*omwk + w1*wk;

            const float* s2 = sv2[c];
            float q000 = s2[a0+b0+d0], q100 = s2[a1+b0+d0];
            float q010 = s2[a0+b1+d0], q110 = s2[a1+b1+d0];
            float q001 = s2[a0+b0+d1], q101 = s2[a1+b0+d1];
            float q011 = s2[a0+b1+d1], q111 = s2[a1+b1+d1];
            float x00 = q000*omwi + q100*wi;
            float x10 = q010*omwi + q110*wi;
            float x01 = q001*omwi + q101*wi;
            float x11 = q011*omwi + q111*wi;
            float y0  = x00*omwj + x10*wj;
            float y1  = x01*omwj + x11*wj;
            float V2  = y0*omwk + y1*wk;

            int col = (int)(V1 * 0.5f);   // v >= 0, trunc == floor
            int row = (int)(V2 * 0.5f);
            off[c] = c*(NJ*HS2) + row*HS + col;
        }

        const int g = I*(G*G) + Jo*G + K;
        #pragma unroll
        for (int j = 0; j < NJ; j++) {
            float acc = 0.0f;
            #pragma unroll
            for (int c = 0; c < NC; c++)
                acc += __ldg(heat + off[c] + j*HS2);
            out[j*G3 + g] = acc * (1.0f/12.0f);
        }
    }
}

extern "C" void kernel_launch(void* const* d_in, const int* in_sizes, int n_in,
                              void* d_out, int out_size) {
    const float* heat   = (const float*)d_in[0];  // (1,C,J,HS,HS)
    const float* center = (const float*)d_in[1];  // (1,3)
    const float* cHM    = (const float*)d_in[2];  // (1,C,2)
    const float* Pm     = (const float*)d_in[3];  // (1,C,4,3)
    const float* Km     = (const float*)d_in[4];  // (1,C,3,3)
    const float* Dm     = (const float*)d_in[5];  // (1,C,1,5)
    float* out = (float*)d_out;                   // (1,J,80,80,80)

    dim3 grid(G/TK, G/TJ, G/TI);  // (5,10,10)
    reproj_kernel<<<grid, NTHREADS>>>(heat, center, cHM, Pm, Km, Dm, out);
}

// round 2
// speedup vs baseline: 1.0194x; 1.0194x over previous
#include <cuda_runtime.h>

// ReprojectionLayer: project 40^3 grid thru 12 cameras, distort, clip,
// trilinear-upsample coords to 80^3, gather 23 joint heatmaps, mean over cams.
//
// R2: heatmaps re-laid-out joint-minor padded to 32 (one 128B line per pixel),
// gathers done as fully-coalesced LDG.128 (1 L1 wavefront per voxel-camera).

#define NC 12
#define NJ 23
#define JP 32            // padded joints (128B line per pixel)
#define HS 130
#define HS2 (HS*HS)      // 16900
#define G  80
#define G2 40
#define G3 (G*G*G)

// Block tile of the 80^3 output
#define TI 8
#define TJ 8
#define TK 16
// Source (40^3) patch needed: T/2 + 2 per axis
#define SI 6
#define SJ 6
#define SK 10
#define NSRC (SI*SJ*SK)   // 360
#define NTHREADS 512

// 12*16900*32 floats = 25.9 MB scratch for transposed/padded heatmaps
__device__ float g_heatT[NC * HS2 * JP];

// ---- Kernel 1: transpose (C,J,HS,HS) -> (C,HS,HS,32) with zero pad ----
__global__ __launch_bounds__(256)
void transpose_kernel(const float* __restrict__ heat) {
    __shared__ float s[NJ][HS];
    const int c   = blockIdx.x / HS;
    const int row = blockIdx.x - c * HS;
    for (int t = threadIdx.x; t < NJ * HS; t += 256) {
        int j = t / HS, col = t - j * HS;
        s[j][col] = heat[((c * NJ + j) * HS + row) * HS + col];
    }
    __syncthreads();
    float* dst = g_heatT + (c * HS + row) * HS * JP;
    for (int t = threadIdx.x; t < HS * JP; t += 256) {
        int col = t >> 5, jj = t & 31;
        dst[t] = (jj < NJ) ? s[jj][col] : 0.0f;
    }
}

// ---- Kernel 2: main ----
__global__ __launch_bounds__(NTHREADS)
void reproj_kernel(const float* __restrict__ center,  // (3)
                   const float* __restrict__ cHM,     // (C,2)
                   const float* __restrict__ Pm,      // (C,4,3)
                   const float* __restrict__ Km,      // (C,3,3)
                   const float* __restrict__ Dm,      // (C,1,5)
                   float* __restrict__ out)           // (J,G,G,G)
{
    __shared__ float sv1[NC][NSRC];
    __shared__ float sv2[NC][NSRC];

    const int tid = threadIdx.x;
    const int bI = blockIdx.z * TI;
    const int bJ = blockIdx.y * TJ;
    const int bK = blockIdx.x * TK;
    const int si0 = bI/2 - 1;
    const int sj0 = bJ/2 - 1;
    const int sk0 = bK/2 - 1;

    const float c0 = center[0], c1 = center[1], c2 = center[2];

    // ---- Phase 1: project the 40^3 source patch for all cameras into smem ----
    for (int t = tid; t < NC*NSRC; t += NTHREADS) {
        int c   = t / NSRC;
        int r   = t - c*NSRC;
        int i   = r / (SJ*SK);
        int rem = r - i*(SJ*SK);
        int jj  = rem / SK;
        int kk  = rem - jj*SK;
        int gi = min(max(si0 + i,  0), G2-1);
        int gj = min(max(sj0 + jj, 0), G2-1);
        int gk = min(max(sk0 + kk, 0), G2-1);
        float X = (float)(gi - 20) * 4.0f + c0;
        float Y = (float)(gj - 20) * 4.0f + c1;
        float Z = (float)(gk - 20) * 4.0f + c2;
        const float* P = Pm + c*12;
        float p0 = X*P[0] + Y*P[3] + Z*P[6] + P[9];
        float p1 = X*P[1] + Y*P[4] + Z*P[7] + P[10];
        float p2 = X*P[2] + Y*P[5] + Z*P[8] + P[11];
        const float* Kc = Km + c*9;
        float fx = Kc[0], fy = Kc[4], cx = Kc[6], cy = Kc[7];
        float k1 = Dm[c*5+0], k2 = Dm[c*5+1];
        float v1 = p0/p2 - cx;
        float v2 = p1/p2 - cy;
        float ra = v1/fx, rb = v2/fy;
        float r2 = ra*ra + rb*rb;
        float dist = 1.0f + (k1 + k2*r2)*r2;
        v1 = v1*dist + cx;
        v2 = v2*dist + cy;
        float chx = cHM[c*2+0], chy = cHM[c*2+1];
        v1 = fminf(fmaxf(v1, chx - 129.0f), chx + 128.0f) - chx + 129.0f;
        v2 = fminf(fmaxf(v2, chy - 129.0f), chy + 128.0f) - chy + 129.0f;
        sv1[c][r] = v1;
        sv2[c][r] = v2;
    }
    __syncthreads();

    const int lane = tid & 31;
    const int q8   = lane & 7;      // 16B piece within the 128B pixel line
    const int vsub = lane >> 3;     // voxel-in-4 for gathering

    // ---- Phase 2: two passes of 512 voxels ----
    #pragma unroll 1
    for (int pass = 0; pass < 2; pass++) {
        const int lv = tid + pass*NTHREADS;     // lane-contiguous voxel id
        {
        const int li = lv >> 7;
        const int lj = (lv >> 4) & 7;
        const int lk = lv & 15;
        const int I  = bI + li;
        const int Jo = bJ + lj;
        const int K  = bK + lk;

        // per-axis interp index + weight (matches align_corners=False upsample2x)
        int i0g, i1g, j0g, j1g, k0g, k1g;
        float wi, wj, wk;
        if (I == 0)        { i0g = 0;      i1g = 1;      wi = 0.f; }
        else if (I == G-1) { i0g = G2-1;   i1g = G2-1;   wi = 0.f; }
        else               { i0g = (I-1)>>1; i1g = i0g+1; wi = (I&1) ? 0.25f : 0.75f; }
        if (Jo == 0)        { j0g = 0;      j1g = 1;      wj = 0.f; }
        else if (Jo == G-1) { j0g = G2-1;   j1g = G2-1;   wj = 0.f; }
        else                { j0g = (Jo-1)>>1; j1g = j0g+1; wj = (Jo&1) ? 0.25f : 0.75f; }
        if (K == 0)        { k0g = 0;      k1g = 1;      wk = 0.f; }
        else if (K == G-1) { k0g = G2-1;   k1g = G2-1;   wk = 0.f; }
        else               { k0g = (K-1)>>1; k1g = k0g+1; wk = (K&1) ? 0.25f : 0.75f; }

        const int a0 = (i0g - si0)*(SJ*SK);
        const int a1 = (i1g - si0)*(SJ*SK);
        const int b0 = (j0g - sj0)*SK;
        const int b1 = (j1g - sj0)*SK;
        const int d0 = k0g - sk0;
        const int d1 = k1g - sk0;
        const float omwi = 1.0f - wi, omwj = 1.0f - wj, omwk = 1.0f - wk;

        int pix[NC];
        #pragma unroll
        for (int c = 0; c < NC; c++) {
            const float* s1 = sv1[c];
            float t000 = s1[a0+b0+d0], t100 = s1[a1+b0+d0];
            float t010 = s1[a0+b1+d0], t110 = s1[a1+b1+d0];
            float t001 = s1[a0+b0+d1], t101 = s1[a1+b0+d1];
            float t011 = s1[a0+b1+d1], t111 = s1[a1+b1+d1];
            float u00 = t000*omwi + t100*wi;
            float u10 = t010*omwi + t110*wi;
            float u01 = t001*omwi + t101*wi;
            float u11 = t011*omwi + t111*wi;
            float w0  = u00*omwj + u10*wj;
            float w1  = u01*omwj + u11*wj;
            float V1  = w0*omwk + w1*wk;

            const float* s2 = sv2[c];
            float q000 = s2[a0+b0+d0], q100 = s2[a1+b0+d0];
            float q010 = s2[a0+b1+d0], q110 = s2[a1+b1+d0];
            float q001 = s2[a0+b0+d1], q101 = s2[a1+b0+d1];
            float q011 = s2[a0+b1+d1], q111 = s2[a1+b1+d1];
            float x00 = q000*omwi + q100*wi;
            float x10 = q010*omwi + q110*wi;
            float x01 = q001*omwi + q101*wi;
            float x11 = q011*omwi + q111*wi;
            float y0  = x00*omwj + x10*wj;
            float y1  = x01*omwj + x11*wj;
            float V2  = y0*omwk + y1*wk;

            int col = (int)(V1 * 0.5f);   // v >= 0, trunc == floor
            int row = (int)(V2 * 0.5f);
            pix[c] = row*HS + col;
        }

        // ---- gather: groups of 4 voxels, one full 128B line per voxel-cam ----
        const int warp_base = (tid & ~31) + pass*NTHREADS;   // first voxel of this warp
        #pragma unroll
        for (int s8 = 0; s8 < 8; s8++) {
            const int dv  = s8*4 + vsub;            // voxel slot [0,32) in warp
            const int lvv = warp_base + dv;
            const int gli = lvv >> 7;
            const int glj = (lvv >> 4) & 7;
            const int glk = lvv & 15;
            const int g = (bI+gli)*(G*G) + (bJ+glj)*G + (bK+glk);

            float4 acc = make_float4(0.f, 0.f, 0.f, 0.f);
            #pragma unroll
            for (int c = 0; c < NC; c++) {
                int p = __shfl_sync(0xffffffffu, pix[c], dv);
                const float4* ptr =
                    reinterpret_cast<const float4*>(g_heatT + ((c*HS2 + p) << 5)) + q8;
                float4 f = __ldg(ptr);
                acc.x += f.x; acc.y += f.y; acc.z += f.z; acc.w += f.w;
            }
            const int j0 = q8 * 4;
            const float inv = 1.0f / 12.0f;
            if (j0     < NJ) out[(j0  )*G3 + g] = acc.x * inv;
            if (j0 + 1 < NJ) out[(j0+1)*G3 + g] = acc.y * inv;
            if (j0 + 2 < NJ) out[(j0+2)*G3 + g] = acc.z * inv;
            if (j0 + 3 < NJ) out[(j0+3)*G3 + g] = acc.w * inv;
        }
        }
    }
}

extern "C" void kernel_launch(void* const* d_in, const int* in_sizes, int n_in,
                              void* d_out, int out_size) {
    const float* heat   = (const float*)d_in[0];  // (1,C,J,HS,HS)
    const float* center = (const float*)d_in[1];  // (1,3)
    const float* cHM    = (const float*)d_in[2];  // (1,C,2)
    const float* Pm     = (const float*)d_in[3];  // (1,C,4,3)
    const float* Km     = (const float*)d_in[4];  // (1,C,3,3)
    const float* Dm     = (const float*)d_in[5];  // (1,C,1,5)
    float* out = (float*)d_out;                   // (1,J,80,80,80)

    transpose_kernel<<<NC*HS, 256>>>(heat);
    dim3 grid(G/TK, G/TJ, G/TI);  // (5,10,10)
    reproj_kernel<<<grid, NTHREADS>>>(center, cHM, Pm, Km, Dm, out);
}

// round 3
// speedup vs baseline: 1.6384x; 1.6072x over previous
#include <cuda_runtime.h>

// ReprojectionLayer: project 40^3 grid thru 12 cameras, distort, clip,
// trilinear-upsample coords to 80^3, gather 23 joint heatmaps, mean over cams.
//
// R3: gather stays line-coalesced (1 L1 line per voxel-camera); accumulators
// are transposed through a bank-conflict-free smem staging tile so the final
// STG.32s are warp-coalesced along the k axis (was ~8 lines per STG in R2).

#define NC 12
#define NJ 23
#define JP 32            // padded joints (128B line per pixel)
#define HS 130
#define HS2 (HS*HS)      // 16900
#define G  80
#define G2 40
#define G3 (G*G*G)

// Block tile of the 80^3 output
#define TI 8
#define TJ 8
#define TK 16
// Source (40^3) patch needed: T/2 + 2 per axis
#define SI 6
#define SJ 6
#define SK 10
#define NSRC (SI*SJ*SK)   // 360
#define NTHREADS 512

#define STAGE_PAD 33      // bank-conflict-free staging row

// dynamic smem layout (floats):
//   sv1:   NC*NSRC            (4320)
//   sv2:   NC*NSRC            (4320)
//   stage: NTHREADS*STAGE_PAD (16896)
#define SMEM_FLOATS (2*NC*NSRC + NTHREADS*STAGE_PAD)
#define SMEM_BYTES  (SMEM_FLOATS * 4)

// 12*16900*32 floats = 25.9 MB scratch for transposed/padded heatmaps
__device__ float g_heatT[NC * HS2 * JP];

// ---- Kernel 1: transpose (C,J,HS,HS) -> (C,HS,HS,32) with zero pad ----
__global__ __launch_bounds__(256)
void transpose_kernel(const float* __restrict__ heat) {
    __shared__ float s[NJ][HS];
    const int c   = blockIdx.x / HS;
    const int row = blockIdx.x - c * HS;
    for (int t = threadIdx.x; t < NJ * HS; t += 256) {
        int j = t / HS, col = t - j * HS;
        s[j][col] = heat[((c * NJ + j) * HS + row) * HS + col];
    }
    __syncthreads();
    float* dst = g_heatT + (c * HS + row) * HS * JP;
    for (int t = threadIdx.x; t < HS * JP; t += 256) {
        int col = t >> 5, jj = t & 31;
        dst[t] = (jj < NJ) ? s[jj][col] : 0.0f;
    }
}

// ---- Kernel 2: main ----
__global__ __launch_bounds__(NTHREADS)
void reproj_kernel(const float* __restrict__ center,  // (3)
                   const float* __restrict__ cHM,     // (C,2)
                   const float* __restrict__ Pm,      // (C,4,3)
                   const float* __restrict__ Km,      // (C,3,3)
                   const float* __restrict__ Dm,      // (C,1,5)
                   float* __restrict__ out)           // (J,G,G,G)
{
    extern __shared__ float dyn[];
    float* sv1   = dyn;                  // [NC][NSRC]
    float* sv2   = dyn + NC*NSRC;        // [NC][NSRC]
    float* stage = dyn + 2*NC*NSRC;      // [NTHREADS][STAGE_PAD]

    const int tid = threadIdx.x;
    const int bI = blockIdx.z * TI;
    const int bJ = blockIdx.y * TJ;
    const int bK = blockIdx.x * TK;
    const int si0 = bI/2 - 1;
    const int sj0 = bJ/2 - 1;
    const int sk0 = bK/2 - 1;

    const float c0 = center[0], c1 = center[1], c2 = center[2];

    // ---- Phase 1: project the 40^3 source patch for all cameras into smem ----
    for (int t = tid; t < NC*NSRC; t += NTHREADS) {
        int c   = t / NSRC;
        int r   = t - c*NSRC;
        int i   = r / (SJ*SK);
        int rem = r - i*(SJ*SK);
        int jj  = rem / SK;
        int kk  = rem - jj*SK;
        int gi = min(max(si0 + i,  0), G2-1);
        int gj = min(max(sj0 + jj, 0), G2-1);
        int gk = min(max(sk0 + kk, 0), G2-1);
        float X = (float)(gi - 20) * 4.0f + c0;
        float Y = (float)(gj - 20) * 4.0f + c1;
        float Z = (float)(gk - 20) * 4.0f + c2;
        const float* P = Pm + c*12;
        float p0 = X*P[0] + Y*P[3] + Z*P[6] + P[9];
        float p1 = X*P[1] + Y*P[4] + Z*P[7] + P[10];
        float p2 = X*P[2] + Y*P[5] + Z*P[8] + P[11];
        const float* Kc = Km + c*9;
        float fx = Kc[0], fy = Kc[4], cx = Kc[6], cy = Kc[7];
        float k1 = Dm[c*5+0], k2 = Dm[c*5+1];
        float v1 = p0/p2 - cx;
        float v2 = p1/p2 - cy;
        float ra = v1/fx, rb = v2/fy;
        float r2 = ra*ra + rb*rb;
        float dist = 1.0f + (k1 + k2*r2)*r2;
        v1 = v1*dist + cx;
        v2 = v2*dist + cy;
        float chx = cHM[c*2+0], chy = cHM[c*2+1];
        v1 = fminf(fmaxf(v1, chx - 129.0f), chx + 128.0f) - chx + 129.0f;
        v2 = fminf(fmaxf(v2, chy - 129.0f), chy + 128.0f) - chy + 129.0f;
        sv1[c*NSRC + r] = v1;
        sv2[c*NSRC + r] = v2;
    }
    __syncthreads();

    const int lane = tid & 31;
    const int q8   = lane & 7;      // 16B piece within the 128B pixel line
    const int vsub = lane >> 3;     // voxel-in-4 for gathering
    float* wstage = stage + (tid & ~31) * STAGE_PAD;  // this warp's 32 voxel rows
    float* tstage = stage + tid * STAGE_PAD;          // this thread's voxel row

    // ---- Phase 2: two passes of 512 voxels ----
    #pragma unroll 1
    for (int pass = 0; pass < 2; pass++) {
        const int lv = tid + pass*NTHREADS;     // lane-contiguous voxel id
        const int li = lv >> 7;
        const int lj = (lv >> 4) & 7;
        const int lk = lv & 15;
        const int I  = bI + li;
        const int Jo = bJ + lj;
        const int K  = bK + lk;

        // per-axis interp index + weight (matches align_corners=False upsample2x)
        int i0g, i1g, j0g, j1g, k0g, k1g;
        float wi, wj, wk;
        if (I == 0)        { i0g = 0;      i1g = 1;      wi = 0.f; }
        else if (I == G-1) { i0g = G2-1;   i1g = G2-1;   wi = 0.f; }
        else               { i0g = (I-1)>>1; i1g = i0g+1; wi = (I&1) ? 0.25f : 0.75f; }
        if (Jo == 0)        { j0g = 0;      j1g = 1;      wj = 0.f; }
        else if (Jo == G-1) { j0g = G2-1;   j1g = G2-1;   wj = 0.f; }
        else                { j0g = (Jo-1)>>1; j1g = j0g+1; wj = (Jo&1) ? 0.25f : 0.75f; }
        if (K == 0)        { k0g = 0;      k1g = 1;      wk = 0.f; }
        else if (K == G-1) { k0g = G2-1;   k1g = G2-1;   wk = 0.f; }
        else               { k0g = (K-1)>>1; k1g = k0g+1; wk = (K&1) ? 0.25f : 0.75f; }

        const int a0 = (i0g - si0)*(SJ*SK);
        const int a1 = (i1g - si0)*(SJ*SK);
        const int b0 = (j0g - sj0)*SK;
        const int b1 = (j1g - sj0)*SK;
        const int d0 = k0g - sk0;
        const int d1 = k1g - sk0;
        const float omwi = 1.0f - wi, omwj = 1.0f - wj, omwk = 1.0f - wk;

        int pix[NC];
        #pragma unroll
        for (int c = 0; c < NC; c++) {
            const float* s1 = sv1 + c*NSRC;
            float t000 = s1[a0+b0+d0], t100 = s1[a1+b0+d0];
            float t010 = s1[a0+b1+d0], t110 = s1[a1+b1+d0];
            float t001 = s1[a0+b0+d1], t101 = s1[a1+b0+d1];
            float t011 = s1[a0+b1+d1], t111 = s1[a1+b1+d1];
            float u00 = t000*omwi + t100*wi;
            float u10 = t010*omwi + t110*wi;
            float u01 = t001*omwi + t101*wi;
            float u11 = t011*omwi + t111*wi;
            float w0  = u00*omwj + u10*wj;
            float w1  = u01*omwj + u11*wj;
            float V1  = w0*omwk + w1*wk;

            const float* s2 = sv2 + c*NSRC;
            float q000 = s2[a0+b0+d0], q100 = s2[a1+b0+d0];
            float q010 = s2[a0+b1+d0], q110 = s2[a1+b1+d0];
            float q001 = s2[a0+b0+d1], q101 = s2[a1+b0+d1];
            float q011 = s2[a0+b1+d1], q111 = s2[a1+b1+d1];
            float x00 = q000*omwi + q100*wi;
            float x10 = q010*omwi + q110*wi;
            float x01 = q001*omwi + q101*wi;
            float x11 = q011*omwi + q111*wi;
            float y0  = x00*omwj + x10*wj;
            float y1  = x01*omwj + x11*wj;
            float V2  = y0*omwk + y1*wk;

            int col = (int)(V1 * 0.5f);   // v >= 0, trunc == floor
            int row = (int)(V2 * 0.5f);
            pix[c] = row*HS + col;
        }

        // ---- gather: groups of 4 voxels, one full 128B line per voxel-cam ----
        #pragma unroll
        for (int s8 = 0; s8 < 8; s8++) {
            const int dv = s8*4 + vsub;            // voxel slot [0,32) in warp
            float4 acc = make_float4(0.f, 0.f, 0.f, 0.f);
            #pragma unroll
            for (int c = 0; c < NC; c++) {
                int p = __shfl_sync(0xffffffffu, pix[c], dv);
                const float4* ptr =
                    reinterpret_cast<const float4*>(g_heatT + ((c*HS2 + p) << 5)) + q8;
                float4 f = __ldg(ptr);
                acc.x += f.x; acc.y += f.y; acc.z += f.z; acc.w += f.w;
            }
            // bank-conflict-free staging write: bank = (dv + 4*q8 + t) mod 32
            float* sp = wstage + dv*STAGE_PAD + q8*4;
            sp[0] = acc.x; sp[1] = acc.y; sp[2] = acc.z; sp[3] = acc.w;
        }
        __syncwarp();

        // ---- coalesced stores: thread owns its voxel, loops joints ----
        const int g = I*(G*G) + Jo*G + K;
        const float inv = 1.0f / 12.0f;
        float* op = out + g;
        #pragma unroll
        for (int j = 0; j < NJ; j++)
            op[j*G3] = tstage[j] * inv;
        __syncwarp();   // staging reuse in next pass (other lanes write my row)
    }
}

extern "C" void kernel_launch(void* const* d_in, const int* in_sizes, int n_in,
                              void* d_out, int out_size) {
    const float* heat   = (const float*)d_in[0];  // (1,C,J,HS,HS)
    const float* center = (const float*)d_in[1];  // (1,3)
    const float* cHM    = (const float*)d_in[2];  // (1,C,2)
    const float* Pm     = (const float*)d_in[3];  // (1,C,4,3)
    const float* Km     = (const float*)d_in[4];  // (1,C,3,3)
    const float* Dm     = (const float*)d_in[5];  // (1,C,1,5)
    float* out = (float*)d_out;                   // (1,J,80,80,80)

    cudaFuncSetAttribute(reproj_kernel,
                         cudaFuncAttributeMaxDynamicSharedMemorySize, SMEM_BYTES);

    transpose_kernel<<<NC*HS, 256>>>(heat);
    dim3 grid(G/TK, G/TJ, G/TI);  // (5,10,10)
    reproj_kernel<<<grid, NTHREADS, SMEM_BYTES>>>(center, cHM, Pm, Km, Dm, out);
}

// round 5
// speedup vs baseline: 1.8352x; 1.1201x over previous
#include <cuda_runtime.h>

// ReprojectionLayer: project 40^3 grid thru 12 cameras, distort, clip,
// trilinear-upsample coords to 80^3, gather 23 joint heatmaps, mean over cams.
//
// R5 (= R4 resubmit after infra failure): tile 8x8x8 single-pass (1000 blocks
// -> ~4% wave imbalance), smem 76KB -> 3 blocks/SM, pad-joint gather lanes
// predicated off, f32x2 packed accumulation, float2-packed coordinate patch.

#define NC 12
#define NJ 23
#define JP 32            // padded joints (128B line per pixel)
#define HS 130
#define HS2 (HS*HS)      // 16900
#define G  80
#define G2 40
#define G3 (G*G*G)

// Block tile of the 80^3 output
#define TT 8             // cubic tile
// Source (40^3) patch: TT/2 + 2 per axis
#define SS 6
#define NSRC (SS*SS*SS)  // 216
#define NTHREADS 512

#define ROW 27           // staging row stride (27 coprime 32 -> conflict-free)

// dynamic smem (floats): sv (float2 packed): NC*NSRC*2 ; stage: NTHREADS*ROW
#define SMEM_FLOATS (2*NC*NSRC + NTHREADS*ROW)
#define SMEM_BYTES  (SMEM_FLOATS * 4)     // 20736 + 55296 = 76032

// 12*16900*32 floats = 25.9 MB scratch for transposed/padded heatmaps
__device__ float g_heatT[NC * HS2 * JP];

// ---- Kernel 1: transpose (C,J,HS,HS) -> (C,HS,HS,32) with zero pad ----
__global__ __launch_bounds__(256)
void transpose_kernel(const float* __restrict__ heat) {
    __shared__ float s[NJ][HS];
    const int c   = blockIdx.x / HS;
    const int row = blockIdx.x - c * HS;
    for (int t = threadIdx.x; t < NJ * HS; t += 256) {
        int j = t / HS, col = t - j * HS;
        s[j][col] = heat[((c * NJ + j) * HS + row) * HS + col];
    }
    __syncthreads();
    float* dst = g_heatT + (c * HS + row) * HS * JP;
    for (int t = threadIdx.x; t < HS * JP; t += 256) {
        int col = t >> 5, jj = t & 31;
        dst[t] = (jj < NJ) ? s[jj][col] : 0.0f;
    }
}

// ---- Kernel 2: main ----
__global__ __launch_bounds__(NTHREADS, 3)
void reproj_kernel(const float* __restrict__ center,  // (3)
                   const float* __restrict__ cHM,     // (C,2)
                   const float* __restrict__ Pm,      // (C,4,3)
                   const float* __restrict__ Km,      // (C,3,3)
                   const float* __restrict__ Dm,      // (C,1,5)
                   float* __restrict__ out)           // (J,G,G,G)
{
    extern __shared__ float dyn[];
    float2* sv   = reinterpret_cast<float2*>(dyn);    // [NC][NSRC] (v1,v2)
    float*  stage = dyn + 2*NC*NSRC;                  // [NTHREADS][ROW]

    const int tid = threadIdx.x;
    const int bI = blockIdx.z * TT;
    const int bJ = blockIdx.y * TT;
    const int bK = blockIdx.x * TT;
    const int si0 = bI/2 - 1;
    const int sj0 = bJ/2 - 1;
    const int sk0 = bK/2 - 1;

    const float c0 = center[0], c1 = center[1], c2 = center[2];

    // ---- Phase 1: project the source patch for all cameras into smem ----
    for (int t = tid; t < NC*NSRC; t += NTHREADS) {
        int c   = t / NSRC;
        int r   = t - c*NSRC;
        int i   = r / (SS*SS);
        int rem = r - i*(SS*SS);
        int jj  = rem / SS;
        int kk  = rem - jj*SS;
        int gi = min(max(si0 + i,  0), G2-1);
        int gj = min(max(sj0 + jj, 0), G2-1);
        int gk = min(max(sk0 + kk, 0), G2-1);
        float X = (float)(gi - 20) * 4.0f + c0;
        float Y = (float)(gj - 20) * 4.0f + c1;
        float Z = (float)(gk - 20) * 4.0f + c2;
        const float* P = Pm + c*12;
        float p0 = X*P[0] + Y*P[3] + Z*P[6] + P[9];
        float p1 = X*P[1] + Y*P[4] + Z*P[7] + P[10];
        float p2 = X*P[2] + Y*P[5] + Z*P[8] + P[11];
        const float* Kc = Km + c*9;
        float fx = Kc[0], fy = Kc[4], cx = Kc[6], cy = Kc[7];
        float k1 = Dm[c*5+0], k2 = Dm[c*5+1];
        float v1 = p0/p2 - cx;
        float v2 = p1/p2 - cy;
        float ra = v1/fx, rb = v2/fy;
        float r2 = ra*ra + rb*rb;
        float dist = 1.0f + (k1 + k2*r2)*r2;
        v1 = v1*dist + cx;
        v2 = v2*dist + cy;
        float chx = cHM[c*2+0], chy = cHM[c*2+1];
        v1 = fminf(fmaxf(v1, chx - 129.0f), chx + 128.0f) - chx + 129.0f;
        v2 = fminf(fmaxf(v2, chy - 129.0f), chy + 128.0f) - chy + 129.0f;
        sv[c*NSRC + r] = make_float2(v1, v2);
    }
    __syncthreads();

    const int lane = tid & 31;
    const int q8   = lane & 7;      // 16B piece within the 128B pixel line
    const int vsub = lane >> 3;     // voxel-in-4 within the gather quad
    float* wstage = stage + (tid & ~31) * ROW;  // this warp's 32 voxel rows
    float* tstage = stage + tid * ROW;          // this thread's voxel row

    // ---- Phase 2 (single pass): one voxel per thread ----
    const int li = tid >> 6;
    const int lj = (tid >> 3) & 7;
    const int lk = tid & 7;
    const int I  = bI + li;
    const int Jo = bJ + lj;
    const int K  = bK + lk;

    // per-axis interp index + weight (matches align_corners=False upsample2x)
    int i0g, i1g, j0g, j1g, k0g, k1g;
    float wi, wj, wk;
    if (I == 0)        { i0g = 0;      i1g = 1;      wi = 0.f; }
    else if (I == G-1) { i0g = G2-1;   i1g = G2-1;   wi = 0.f; }
    else               { i0g = (I-1)>>1; i1g = i0g+1; wi = (I&1) ? 0.25f : 0.75f; }
    if (Jo == 0)        { j0g = 0;      j1g = 1;      wj = 0.f; }
    else if (Jo == G-1) { j0g = G2-1;   j1g = G2-1;   wj = 0.f; }
    else                { j0g = (Jo-1)>>1; j1g = j0g+1; wj = (Jo&1) ? 0.25f : 0.75f; }
    if (K == 0)        { k0g = 0;      k1g = 1;      wk = 0.f; }
    else if (K == G-1) { k0g = G2-1;   k1g = G2-1;   wk = 0.f; }
    else               { k0g = (K-1)>>1; k1g = k0g+1; wk = (K&1) ? 0.25f : 0.75f; }

    const int a0 = (i0g - si0)*(SS*SS);
    const int a1 = (i1g - si0)*(SS*SS);
    const int b0 = (j0g - sj0)*SS;
    const int b1 = (j1g - sj0)*SS;
    const int d0 = k0g - sk0;
    const int d1 = k1g - sk0;
    const float omwi = 1.0f - wi, omwj = 1.0f - wj, omwk = 1.0f - wk;

    int pix[NC];
    #pragma unroll
    for (int c = 0; c < NC; c++) {
        const float2* s = sv + c*NSRC;
        float2 t000 = s[a0+b0+d0], t100 = s[a1+b0+d0];
        float2 t010 = s[a0+b1+d0], t110 = s[a1+b1+d0];
        float2 t001 = s[a0+b0+d1], t101 = s[a1+b0+d1];
        float2 t011 = s[a0+b1+d1], t111 = s[a1+b1+d1];

        float u00 = t000.x*omwi + t100.x*wi;
        float u10 = t010.x*omwi + t110.x*wi;
        float u01 = t001.x*omwi + t101.x*wi;
        float u11 = t011.x*omwi + t111.x*wi;
        float w0  = u00*omwj + u10*wj;
        float w1  = u01*omwj + u11*wj;
        float V1  = w0*omwk + w1*wk;

        float x00 = t000.y*omwi + t100.y*wi;
        float x10 = t010.y*omwi + t110.y*wi;
        float x01 = t001.y*omwi + t101.y*wi;
        float x11 = t011.y*omwi + t111.y*wi;
        float y0  = x00*omwj + x10*wj;
        float y1  = x01*omwj + x11*wj;
        float V2  = y0*omwk + y1*wk;

        int col = (int)(V1 * 0.5f);   // v >= 0, trunc == floor
        int row = (int)(V2 * 0.5f);
        pix[c] = (c*HS2 + row*HS + col) << 5;   // word offset of 128B pixel line
    }

    // ---- gather: quads of 4 voxels; lanes q8<6 fetch the 23 real joints ----
    const bool active = (q8 < 6);
    #pragma unroll
    for (int s8 = 0; s8 < 8; s8++) {
        const int dv = s8*4 + vsub;            // voxel slot [0,32) in warp
        unsigned long long a0p = 0ull, a1p = 0ull;   // packed f32x2 accumulators
        #pragma unroll
        for (int c = 0; c < NC; c++) {
            int base = __shfl_sync(0xffffffffu, pix[c], dv);
            if (active) {
                const ulonglong2* ptr =
                    reinterpret_cast<const ulonglong2*>(g_heatT + base + q8*4);
                ulonglong2 v = __ldg(ptr);
                asm("add.rn.f32x2 %0, %0, %1;" : "+l"(a0p) : "l"(v.x));
                asm("add.rn.f32x2 %0, %0, %1;" : "+l"(a1p) : "l"(v.y));
            }
        }
        if (active) {
            float* sp = wstage + dv*ROW + q8*4;
            sp[0] = __uint_as_float((unsigned)(a0p));
            sp[1] = __uint_as_float((unsigned)(a0p >> 32));
            sp[2] = __uint_as_float((unsigned)(a1p));
            sp[3] = __uint_as_float((unsigned)(a1p >> 32));
        }
    }
    __syncwarp();

    // ---- coalesced stores: thread owns its voxel, loops joints ----
    const int g = I*(G*G) + Jo*G + K;
    const float inv = 1.0f / 12.0f;
    float* op = out + g;
    #pragma unroll
    for (int j = 0; j < NJ; j++)
        op[j*G3] = tstage[j] * inv;
}

extern "C" void kernel_launch(void* const* d_in, const int* in_sizes, int n_in,
                              void* d_out, int out_size) {
    const float* heat   = (const float*)d_in[0];  // (1,C,J,HS,HS)
    const float* center = (const float*)d_in[1];  // (1,3)
    const float* cHM    = (const float*)d_in[2];  // (1,C,2)
    const float* Pm     = (const float*)d_in[3];  // (1,C,4,3)
    const float* Km     = (const float*)d_in[4];  // (1,C,3,3)
    const float* Dm     = (const float*)d_in[5];  // (1,C,1,5)
    float* out = (float*)d_out;                   // (1,J,80,80,80)

    cudaFuncSetAttribute(reproj_kernel,
                         cudaFuncAttributeMaxDynamicSharedMemorySize, SMEM_BYTES);

    transpose_kernel<<<NC*HS, 256>>>(heat);
    dim3 grid(G/TT, G/TT, G/TT);  // (10,10,10)
    reproj_kernel<<<grid, NTHREADS, SMEM_BYTES>>>(center, cHM, Pm, Km, Dm, out);
}